// round 11
// baseline (speedup 1.0000x reference)
#include <cuda_runtime.h>
#include <cuda_fp16.h>
#include <math.h>

#define NF 128
#define HID 64
#define MAXN 50000
#define MAXE 800000
#define MAXG 64
#define BN_EPS 1e-5f

// ---- static scratch ----
__device__ int    g_cnt   [MAXN];
__device__ int    g_rowptr[MAXN];
__device__ int    g_cursor[MAXN];
__device__ float  g_dinv  [MAXN];
__device__ int    g_csr   [MAXE];
__device__ float  g_id    [MAXN * HID];    // fp32 input projection (residual)
__device__ __half g_hp    [MAXN * HID];    // fp16 pre-scaled (h@W)*dinv
__device__ float  g_h     [MAXN * HID];    // fp32 layer state
__device__ float  g_sums  [MAXG * HID];
__device__ float  g_cnts  [MAXG];

__device__ __forceinline__ void red_add_v2(float* addr, float a, float b) {
    asm volatile("red.global.add.v2.f32 [%0], {%1,%2};"
                 :: "l"(addr), "f"(a), "f"(b) : "memory");
}

// ---------------- setup ----------------
__global__ void k_init(int N) {
    int i = blockIdx.x * blockDim.x + threadIdx.x;
    if (i < N) g_cnt[i] = 0;
}

__global__ void k_hist(const int* __restrict__ dst, int E, int G) {
    int i = blockIdx.x * blockDim.x + threadIdx.x;
    int e = i * 4;
    if (e + 3 < E) {
        int d0 = dst[e], d1 = dst[e + 1], d2 = dst[e + 2], d3 = dst[e + 3];
        atomicAdd(&g_cnt[d0], 1);
        atomicAdd(&g_cnt[d1], 1);
        atomicAdd(&g_cnt[d2], 1);
        atomicAdd(&g_cnt[d3], 1);
    } else {
        for (int j = e; j < E; j++) atomicAdd(&g_cnt[dst[j]], 1);
    }
    if (i < G * HID) g_sums[i] = 0.0f;
    if (i < G) g_cnts[i] = 0.0f;
}

// single-block exclusive scan of g_cnt -> rowptr/cursor + dinv
__global__ void k_scanall(int N) {
    __shared__ int sh[1024];
    const int t = threadIdx.x;
    const int per = (N + 1023) / 1024;
    const int base = t * per;
    int s = 0;
    for (int i = 0; i < per; i++) {
        int idx = base + i;
        if (idx < N) s += g_cnt[idx];
    }
    sh[t] = s;
    __syncthreads();
    for (int off = 1; off < 1024; off <<= 1) {
        int v = (t >= off) ? sh[t - off] : 0;
        __syncthreads();
        sh[t] += v;
        __syncthreads();
    }
    int run = sh[t] - s;
    for (int i = 0; i < per; i++) {
        int idx = base + i;
        if (idx < N) {
            int c = g_cnt[idx];
            g_rowptr[idx] = run;
            g_cursor[idx] = run;
            g_dinv[idx]   = rsqrtf((float)c + 1.0f);  // +1 self-loop
            run += c;
        }
    }
}

__global__ void k_fill(const int* __restrict__ src, const int* __restrict__ dst, int E) {
    int i = blockIdx.x * blockDim.x + threadIdx.x;
    int e = i * 4;
    if (e + 3 < E) {
        int d0 = dst[e], d1 = dst[e + 1], d2 = dst[e + 2], d3 = dst[e + 3];
        int s0 = src[e], s1 = src[e + 1], s2 = src[e + 2], s3 = src[e + 3];
        int p0 = atomicAdd(&g_cursor[d0], 1);
        int p1 = atomicAdd(&g_cursor[d1], 1);
        int p2 = atomicAdd(&g_cursor[d2], 1);
        int p3 = atomicAdd(&g_cursor[d3], 1);
        g_csr[p0] = s0; g_csr[p1] = s1; g_csr[p2] = s2; g_csr[p3] = s3;
    } else {
        for (int j = e; j < E; j++) {
            int p = atomicAdd(&g_cursor[dst[j]], 1);
            g_csr[p] = src[j];
        }
    }
}

// ------- fused dual GEMM (K=128): id = X@W_in^T (fp32), hp = (X@W1^T)*dinv (fp16)
// 256 threads, 64 nodes/block, 128 output feats. Thread = 4 nodes x 8 feats.
// X staged once into smem; W-loads are 512B-contiguous per warp (conflict-free).
#define XRS0 132
#define WRS0 136
__global__ void __launch_bounds__(256) k_gemm0(const float* __restrict__ X,
                                               const float* __restrict__ W_in,
                                               const float* __restrict__ W1,
                                               int N) {
    extern __shared__ float sm0[];
    float* Xs = sm0;               // [64][XRS0]
    float* Wt = sm0 + 64 * XRS0;   // [128][WRS0]: Wt[k][f]

    const int tid = threadIdx.x;
    const int nbase = blockIdx.x * 64;

    for (int idx = tid; idx < 128 * 128; idx += 256) {
        int f = idx >> 7;
        int k = idx & 127;
        float v = (f < 64) ? W_in[f * 128 + k] : W1[(f - 64) * 128 + k];
        Wt[k * WRS0 + f] = v;
    }
    for (int idx = tid; idx < 64 * 32; idx += 256) {
        int node = idx >> 5;
        int kq = (idx & 31) * 4;
        int gn = nbase + node;
        float4 v = (gn < N) ? *(const float4*)(X + (size_t)gn * 128 + kq)
                            : make_float4(0.f, 0.f, 0.f, 0.f);
        *(float4*)&Xs[node * XRS0 + kq] = v;
    }
    __syncthreads();

    const int fg8 = (tid & 15) * 8;   // 0..120
    const int nl  = tid >> 4;         // 0..15

    float acc[4][8];
#pragma unroll
    for (int m = 0; m < 4; m++)
#pragma unroll
        for (int c = 0; c < 8; c++) acc[m][c] = 0.f;

#define G0_STEP(J, COMP)                                                \
    {                                                                   \
        float4 w0 = *(const float4*)&Wt[(k0 + J) * WRS0 + fg8];         \
        float4 w1 = *(const float4*)&Wt[(k0 + J) * WRS0 + fg8 + 4];     \
        _Pragma("unroll")                                               \
        for (int m = 0; m < 4; m++) {                                   \
            float xs = xv[m].COMP;                                      \
            acc[m][0] = fmaf(xs, w0.x, acc[m][0]);                      \
            acc[m][1] = fmaf(xs, w0.y, acc[m][1]);                      \
            acc[m][2] = fmaf(xs, w0.z, acc[m][2]);                      \
            acc[m][3] = fmaf(xs, w0.w, acc[m][3]);                      \
            acc[m][4] = fmaf(xs, w1.x, acc[m][4]);                      \
            acc[m][5] = fmaf(xs, w1.y, acc[m][5]);                      \
            acc[m][6] = fmaf(xs, w1.z, acc[m][6]);                      \
            acc[m][7] = fmaf(xs, w1.w, acc[m][7]);                      \
        }                                                               \
    }

#pragma unroll 4
    for (int k0 = 0; k0 < 128; k0 += 4) {
        float4 xv[4];
#pragma unroll
        for (int m = 0; m < 4; m++)
            xv[m] = *(const float4*)&Xs[(m * 16 + nl) * XRS0 + k0];
        G0_STEP(0, x)
        G0_STEP(1, y)
        G0_STEP(2, z)
        G0_STEP(3, w)
    }
#undef G0_STEP

#pragma unroll
    for (int m = 0; m < 4; m++) {
        int gn = nbase + m * 16 + nl;
        if (gn >= N) continue;
        if (fg8 < 64) {
            float* O = g_id + (size_t)gn * HID + fg8;
            *(float4*)O       = make_float4(acc[m][0], acc[m][1], acc[m][2], acc[m][3]);
            *(float4*)(O + 4) = make_float4(acc[m][4], acc[m][5], acc[m][6], acc[m][7]);
        } else {
            float s = g_dinv[gn];
            __half2 h0 = __floats2half2_rn(acc[m][0] * s, acc[m][1] * s);
            __half2 h1 = __floats2half2_rn(acc[m][2] * s, acc[m][3] * s);
            __half2 h2 = __floats2half2_rn(acc[m][4] * s, acc[m][5] * s);
            __half2 h3 = __floats2half2_rn(acc[m][6] * s, acc[m][7] * s);
            uint4 pk = make_uint4(*(unsigned*)&h0, *(unsigned*)&h1,
                                  *(unsigned*)&h2, *(unsigned*)&h3);
            *(uint4*)(g_hp + (size_t)gn * HID + (fg8 - 64)) = pk;
        }
    }
}

// ------- layer GEMM (K=64): hp = (h@W^T)*dinv (fp16) -------
// 256 threads, 128 nodes/block, thread = 4 nodes x 8 feats.
#define XRS1 68
#define WRS1 72
__global__ void __launch_bounds__(256) k_gemm64(const float* __restrict__ X,
                                                const float* __restrict__ W,
                                                int N) {
    __shared__ float Xs[128 * XRS1];
    __shared__ float Wt[64 * WRS1];   // Wt[k][f]

    const int tid = threadIdx.x;
    const int nbase = blockIdx.x * 128;

    for (int idx = tid; idx < 64 * 64; idx += 256) {
        int f = idx >> 6;
        int k = idx & 63;
        Wt[k * WRS1 + f] = W[idx];
    }
    for (int idx = tid; idx < 128 * 16; idx += 256) {
        int node = idx >> 4;
        int kq = (idx & 15) * 4;
        int gn = nbase + node;
        float4 v = (gn < N) ? *(const float4*)(X + (size_t)gn * 64 + kq)
                            : make_float4(0.f, 0.f, 0.f, 0.f);
        *(float4*)&Xs[node * XRS1 + kq] = v;
    }
    __syncthreads();

    const int fg8 = (tid & 7) * 8;    // 0..56
    const int nl  = tid >> 3;         // 0..31

    float acc[4][8];
#pragma unroll
    for (int m = 0; m < 4; m++)
#pragma unroll
        for (int c = 0; c < 8; c++) acc[m][c] = 0.f;

#define G1_STEP(J, COMP)                                                \
    {                                                                   \
        float4 w0 = *(const float4*)&Wt[(k0 + J) * WRS1 + fg8];         \
        float4 w1 = *(const float4*)&Wt[(k0 + J) * WRS1 + fg8 + 4];     \
        _Pragma("unroll")                                               \
        for (int m = 0; m < 4; m++) {                                   \
            float xs = xv[m].COMP;                                      \
            acc[m][0] = fmaf(xs, w0.x, acc[m][0]);                      \
            acc[m][1] = fmaf(xs, w0.y, acc[m][1]);                      \
            acc[m][2] = fmaf(xs, w0.z, acc[m][2]);                      \
            acc[m][3] = fmaf(xs, w0.w, acc[m][3]);                      \
            acc[m][4] = fmaf(xs, w1.x, acc[m][4]);                      \
            acc[m][5] = fmaf(xs, w1.y, acc[m][5]);                      \
            acc[m][6] = fmaf(xs, w1.z, acc[m][6]);                      \
            acc[m][7] = fmaf(xs, w1.w, acc[m][7]);                      \
        }                                                               \
    }

#pragma unroll 4
    for (int k0 = 0; k0 < 64; k0 += 4) {
        float4 xv[4];
#pragma unroll
        for (int m = 0; m < 4; m++)
            xv[m] = *(const float4*)&Xs[(m * 32 + nl) * XRS1 + k0];
        G1_STEP(0, x)
        G1_STEP(1, y)
        G1_STEP(2, z)
        G1_STEP(3, w)
    }
#undef G1_STEP

#pragma unroll
    for (int m = 0; m < 4; m++) {
        int gn = nbase + m * 32 + nl;
        if (gn >= N) continue;
        float s = g_dinv[gn];
        __half2 h0 = __floats2half2_rn(acc[m][0] * s, acc[m][1] * s);
        __half2 h1 = __floats2half2_rn(acc[m][2] * s, acc[m][3] * s);
        __half2 h2 = __floats2half2_rn(acc[m][4] * s, acc[m][5] * s);
        __half2 h3 = __floats2half2_rn(acc[m][6] * s, acc[m][7] * s);
        uint4 pk = make_uint4(*(unsigned*)&h0, *(unsigned*)&h1,
                              *(unsigned*)&h2, *(unsigned*)&h3);
        *(uint4*)(g_hp + (size_t)gn * HID + fg8) = pk;
    }
}

// ---------------- fused aggregate + epilogue (+ optional pool) -----------
__global__ void __launch_bounds__(256) k_agg(
        const __half* __restrict__ hp, const float* __restrict__ resid,
        const float* __restrict__ bias, const float* __restrict__ gamma,
        const float* __restrict__ beta, const float* __restrict__ mean,
        const float* __restrict__ var,
        float* __restrict__ hout, const int* __restrict__ batch, int N) {
    int n = (blockIdx.x * blockDim.x + threadIdx.x) >> 5;
    if (n >= N) return;
    const int lane = threadIdx.x & 31;
    const int f = lane * 2;

    const int  start = g_rowptr[n];
    const int  len   = g_cnt[n];
    const int* cs    = g_csr + start;

    float ax = 0.f, ay = 0.f, bx = 0.f, by = 0.f;
    int j = 0;
    for (; j + 8 <= len; j += 8) {
        int s0 = cs[j],     s1 = cs[j + 1], s2 = cs[j + 2], s3 = cs[j + 3];
        int s4 = cs[j + 4], s5 = cs[j + 5], s6 = cs[j + 6], s7 = cs[j + 7];
        float2 v0 = __half22float2(*(const __half2*)(hp + (size_t)s0 * HID + f));
        float2 v1 = __half22float2(*(const __half2*)(hp + (size_t)s1 * HID + f));
        float2 v2 = __half22float2(*(const __half2*)(hp + (size_t)s2 * HID + f));
        float2 v3 = __half22float2(*(const __half2*)(hp + (size_t)s3 * HID + f));
        float2 v4 = __half22float2(*(const __half2*)(hp + (size_t)s4 * HID + f));
        float2 v5 = __half22float2(*(const __half2*)(hp + (size_t)s5 * HID + f));
        float2 v6 = __half22float2(*(const __half2*)(hp + (size_t)s6 * HID + f));
        float2 v7 = __half22float2(*(const __half2*)(hp + (size_t)s7 * HID + f));
        ax += (v0.x + v1.x) + (v4.x + v5.x);
        ay += (v0.y + v1.y) + (v4.y + v5.y);
        bx += (v2.x + v3.x) + (v6.x + v7.x);
        by += (v2.y + v3.y) + (v6.y + v7.y);
    }
    for (; j + 4 <= len; j += 4) {
        int s0 = cs[j], s1 = cs[j + 1], s2 = cs[j + 2], s3 = cs[j + 3];
        float2 v0 = __half22float2(*(const __half2*)(hp + (size_t)s0 * HID + f));
        float2 v1 = __half22float2(*(const __half2*)(hp + (size_t)s1 * HID + f));
        float2 v2 = __half22float2(*(const __half2*)(hp + (size_t)s2 * HID + f));
        float2 v3 = __half22float2(*(const __half2*)(hp + (size_t)s3 * HID + f));
        ax += v0.x + v1.x;
        ay += v0.y + v1.y;
        bx += v2.x + v3.x;
        by += v2.y + v3.y;
    }
    for (; j < len; j++) {
        int s = cs[j];
        float2 v = __half22float2(*(const __half2*)(hp + (size_t)s * HID + f));
        ax += v.x;
        ay += v.y;
    }
    ax += bx; ay += by;

    float di = g_dinv[n];
    float2 p = __half22float2(*(const __half2*)(hp + (size_t)n * HID + f));
    float vx = (ax + p.x) * di + bias[f];
    float vy = (ay + p.y) * di + bias[f + 1];
    vx = (vx - mean[f])     * (gamma[f]     * rsqrtf(var[f]     + BN_EPS)) + beta[f];
    vy = (vy - mean[f + 1]) * (gamma[f + 1] * rsqrtf(var[f + 1] + BN_EPS)) + beta[f + 1];
    vx = fmaxf(vx, 0.f);
    vy = fmaxf(vy, 0.f);
    if (resid) {
        float2 r = *(const float2*)(resid + (size_t)n * HID + f);
        vx += r.x; vy += r.y;
    }
    if (hout)
        *(float2*)(hout + (size_t)n * HID + f) = make_float2(vx, vy);
    if (batch) {
        int g = batch[n];
        red_add_v2(&g_sums[(size_t)g * HID + f], vx, vy);
        if (lane == 0) atomicAdd(&g_cnts[g], 1.0f);
    }
}

// ---------------- final linear ----------------
__global__ void k_final(const float* __restrict__ lin_w, const float* __restrict__ lin_b,
                        float* __restrict__ out, int G) {
    int g = blockIdx.x * blockDim.x + threadIdx.x;
    if (g >= G) return;
    float c = fmaxf(g_cnts[g], 1.0f);
    float acc = 0.f;
#pragma unroll
    for (int f = 0; f < HID; f++) acc += g_sums[g * HID + f] * lin_w[f];
    out[g] = acc / c + lin_b[0];
}

// ---------------- host launcher ----------------
extern "C" void kernel_launch(void* const* d_in, const int* in_sizes, int n_in,
                              void* d_out, int out_size) {
    const float* x     = (const float*)d_in[0];
    const int*   ei    = (const int*)  d_in[1];
    const int*   batch = (const int*)  d_in[2];
    const float* W_in  = (const float*)d_in[3];
    const float* W1    = (const float*)d_in[4];
    const float* b1    = (const float*)d_in[5];
    const float* Ws    = (const float*)d_in[6];
    const float* bs    = (const float*)d_in[7];
    const float* bn_g  = (const float*)d_in[8];
    const float* bn_b  = (const float*)d_in[9];
    const float* bn_m  = (const float*)d_in[10];
    const float* bn_v  = (const float*)d_in[11];
    const float* lin_w = (const float*)d_in[12];
    const float* lin_b = (const float*)d_in[13];
    float* out = (float*)d_out;

    const int N = in_sizes[0] / NF;
    const int E = in_sizes[1] / 2;
    const int G = out_size;
    const int* src = ei;
    const int* dst = ei + E;

    float  *p_id, *p_h;
    cudaGetSymbolAddress((void**)&p_id, g_id);
    cudaGetSymbolAddress((void**)&p_h,  g_h);
    __half *p_hp;
    cudaGetSymbolAddress((void**)&p_hp, g_hp);

    const int smem0 = (64 * XRS0 + 128 * WRS0) * 4;   // 103424 B
    static bool attr_done = false;
    if (!attr_done) {
        cudaFuncSetAttribute(k_gemm0, cudaFuncAttributeMaxDynamicSharedMemorySize, smem0);
        attr_done = true;
    }

    const int thr = 256;
    const int eb4 = (E / 4 + thr - 1) / thr + 1;

    k_init   <<<(N + thr - 1) / thr, thr>>>(N);
    k_hist   <<<eb4, thr>>>(dst, E, G);
    k_scanall<<<1, 1024>>>(N);
    k_gemm0  <<<(N + 63) / 64, 256, smem0>>>(x, W_in, W1, N);   // 4th launch: profiled
    k_fill   <<<eb4, thr>>>(src, dst, E);

    const int g64B = (N + 127) / 128;
    const int aggB = (N * 32 + thr - 1) / thr;
    for (int layer = 0; layer < 5; layer++) {
        if (layer > 0)
            k_gemm64<<<g64B, 256>>>(p_h, Ws + (size_t)(layer - 1) * HID * HID, N);
        const float* bias  = (layer == 0) ? b1 : bs + (size_t)(layer - 1) * HID;
        const float* resid = (layer == 0) ? p_id : (layer < 4 ? p_h : nullptr);
        float*       hout  = (layer < 4) ? p_h : nullptr;
        const int*   bptr  = (layer == 4) ? batch : nullptr;
        k_agg<<<aggB, thr>>>(p_hp, resid, bias,
                             bn_g + layer * HID, bn_b + layer * HID,
                             bn_m + layer * HID, bn_v + layer * HID,
                             hout, bptr, N);
    }

    k_final<<<1, ((G + 31) / 32) * 32>>>(lin_w, lin_b, out, G);
}

// round 12
// speedup vs baseline: 1.0737x; 1.0737x over previous
#include <cuda_runtime.h>
#include <cuda_fp16.h>
#include <math.h>

#define NF 128
#define HID 64
#define MAXN 50000
#define MAXE 800000
#define MAXG 64
#define BN_EPS 1e-5f

// ---- static scratch ----
__device__ int    g_cnt   [MAXN];
__device__ int    g_rowptr[MAXN];
__device__ int    g_cursor[MAXN];
__device__ float  g_dinv  [MAXN];
__device__ int    g_csr   [MAXE];
__device__ float  g_id    [MAXN * HID];    // fp32 input projection (residual)
__device__ __half g_hp    [MAXN * HID];    // fp16 pre-scaled (h@W)*dinv
__device__ float  g_h     [MAXN * HID];    // fp32 layer state
__device__ float  g_sums  [MAXG * HID];
__device__ float  g_cnts  [MAXG];

__device__ __forceinline__ void red_add_v2(float* addr, float a, float b) {
    asm volatile("red.global.add.v2.f32 [%0], {%1,%2};"
                 :: "l"(addr), "f"(a), "f"(b) : "memory");
}

// ---------------- setup ----------------
__global__ void k_hist(const int* __restrict__ dst, int E, int G) {
    int i = blockIdx.x * blockDim.x + threadIdx.x;
    int e = i * 4;
    if (e + 3 < E) {
        int d0 = dst[e], d1 = dst[e + 1], d2 = dst[e + 2], d3 = dst[e + 3];
        atomicAdd(&g_cnt[d0], 1);
        atomicAdd(&g_cnt[d1], 1);
        atomicAdd(&g_cnt[d2], 1);
        atomicAdd(&g_cnt[d3], 1);
    } else {
        for (int j = e; j < E; j++) atomicAdd(&g_cnt[dst[j]], 1);
    }
    if (i < G * HID) g_sums[i] = 0.0f;
    if (i < G) g_cnts[i] = 0.0f;
}

// single-block exclusive scan of g_cnt -> rowptr/cursor + dinv
__global__ void k_scanall(int N) {
    __shared__ int sh[1024];
    const int t = threadIdx.x;
    const int per = (N + 1023) / 1024;
    const int base = t * per;
    int s = 0;
    for (int i = 0; i < per; i++) {
        int idx = base + i;
        if (idx < N) s += g_cnt[idx];
    }
    sh[t] = s;
    __syncthreads();
    for (int off = 1; off < 1024; off <<= 1) {
        int v = (t >= off) ? sh[t - off] : 0;
        __syncthreads();
        sh[t] += v;
        __syncthreads();
    }
    int run = sh[t] - s;
    for (int i = 0; i < per; i++) {
        int idx = base + i;
        if (idx < N) {
            int c = g_cnt[idx];
            g_rowptr[idx] = run;
            g_cursor[idx] = run;
            g_dinv[idx]   = rsqrtf((float)c + 1.0f);  // +1 self-loop
            run += c;
        }
    }
}

__global__ void k_fill(const int* __restrict__ src, const int* __restrict__ dst, int E) {
    int i = blockIdx.x * blockDim.x + threadIdx.x;
    int e = i * 4;
    if (e + 3 < E) {
        int d0 = dst[e], d1 = dst[e + 1], d2 = dst[e + 2], d3 = dst[e + 3];
        int s0 = src[e], s1 = src[e + 1], s2 = src[e + 2], s3 = src[e + 3];
        int p0 = atomicAdd(&g_cursor[d0], 1);
        int p1 = atomicAdd(&g_cursor[d1], 1);
        int p2 = atomicAdd(&g_cursor[d2], 1);
        int p3 = atomicAdd(&g_cursor[d3], 1);
        g_csr[p0] = s0; g_csr[p1] = s1; g_csr[p2] = s2; g_csr[p3] = s3;
    } else {
        for (int j = e; j < E; j++) {
            int p = atomicAdd(&g_cursor[dst[j]], 1);
            g_csr[p] = src[j];
        }
    }
}

// ------- fused dual GEMM (K=128): id = X@W_in^T (fp32), hp = (X@W1^T)*dinv (fp16)
// 512 threads, 64 nodes/block, 128 output feats, thread = 4 nodes x 4 feats.
// X staged once into smem (row-major padded -> warp-uniform broadcast LDS).
#define XRS0 132
#define WRS0 136
__global__ void __launch_bounds__(512) k_gemm0(const float* __restrict__ X,
                                               const float* __restrict__ W_in,
                                               const float* __restrict__ W1,
                                               int N) {
    extern __shared__ float sm0[];
    float* Xs = sm0;               // [64][XRS0]
    float* Wt = sm0 + 64 * XRS0;   // [128][WRS0]: Wt[k][f]

    const int tid = threadIdx.x;
    const int nbase = blockIdx.x * 64;

    for (int idx = tid; idx < 128 * 128; idx += 512) {
        int f = idx >> 7;
        int k = idx & 127;
        float v = (f < 64) ? W_in[f * 128 + k] : W1[(f - 64) * 128 + k];
        Wt[k * WRS0 + f] = v;
    }
    for (int idx = tid; idx < 64 * 32; idx += 512) {
        int node = idx >> 5;
        int kq = (idx & 31) * 4;
        int gn = nbase + node;
        float4 v = (gn < N) ? *(const float4*)(X + (size_t)gn * 128 + kq)
                            : make_float4(0.f, 0.f, 0.f, 0.f);
        *(float4*)&Xs[node * XRS0 + kq] = v;
    }
    __syncthreads();

    const int fg4 = (tid & 31) * 4;   // 0..124
    const int nl  = tid >> 5;         // 0..15 (warp-uniform)

    float4 acc[4];
#pragma unroll
    for (int m = 0; m < 4; m++) acc[m] = make_float4(0.f, 0.f, 0.f, 0.f);

#define G0_STEP(J, COMP)                                                \
    {                                                                   \
        float4 w = *(const float4*)&Wt[(k0 + J) * WRS0 + fg4];          \
        _Pragma("unroll")                                               \
        for (int m = 0; m < 4; m++) {                                   \
            float xs = xv[m].COMP;                                      \
            acc[m].x = fmaf(xs, w.x, acc[m].x);                         \
            acc[m].y = fmaf(xs, w.y, acc[m].y);                         \
            acc[m].z = fmaf(xs, w.z, acc[m].z);                         \
            acc[m].w = fmaf(xs, w.w, acc[m].w);                         \
        }                                                               \
    }

#pragma unroll 4
    for (int k0 = 0; k0 < 128; k0 += 4) {
        float4 xv[4];
#pragma unroll
        for (int m = 0; m < 4; m++)
            xv[m] = *(const float4*)&Xs[(m * 16 + nl) * XRS0 + k0];
        G0_STEP(0, x)
        G0_STEP(1, y)
        G0_STEP(2, z)
        G0_STEP(3, w)
    }
#undef G0_STEP

#pragma unroll
    for (int m = 0; m < 4; m++) {
        int gn = nbase + m * 16 + nl;
        if (gn >= N) continue;
        if (fg4 < 64) {
            *(float4*)(g_id + (size_t)gn * HID + fg4) = acc[m];
        } else {
            float s = g_dinv[gn];
            __half2* o = (__half2*)(g_hp + (size_t)gn * HID + (fg4 - 64));
            o[0] = __floats2half2_rn(acc[m].x * s, acc[m].y * s);
            o[1] = __floats2half2_rn(acc[m].z * s, acc[m].w * s);
        }
    }
}

// ------- layer GEMM (K=64): hp = (h@W^T)*dinv (fp16); X staged in smem -----
#define XRS1 68
#define WRS1 72
__global__ void __launch_bounds__(256) k_gemm64(const float* __restrict__ X,
                                                const float* __restrict__ W,
                                                int N) {
    __shared__ float Xs[64 * XRS1];
    __shared__ float Wt[64 * WRS1];   // Wt[k][f]

    const int tid = threadIdx.x;
    const int nbase = blockIdx.x * 64;

    for (int idx = tid; idx < 64 * 64; idx += 256) {
        int f = idx >> 6;
        int k = idx & 63;
        Wt[k * WRS1 + f] = W[idx];
    }
    for (int idx = tid; idx < 64 * 16; idx += 256) {
        int node = idx >> 4;
        int kq = (idx & 15) * 4;
        int gn = nbase + node;
        float4 v = (gn < N) ? *(const float4*)(X + (size_t)gn * 64 + kq)
                            : make_float4(0.f, 0.f, 0.f, 0.f);
        *(float4*)&Xs[node * XRS1 + kq] = v;
    }
    __syncthreads();

    const int fg4 = (tid & 15) * 4;   // 0..60
    const int nl  = tid >> 4;         // 0..15

    float4 acc[4];
#pragma unroll
    for (int m = 0; m < 4; m++) acc[m] = make_float4(0.f, 0.f, 0.f, 0.f);

#define G1_STEP(J, COMP)                                                \
    {                                                                   \
        float4 w = *(const float4*)&Wt[(k0 + J) * WRS1 + fg4];          \
        _Pragma("unroll")                                               \
        for (int m = 0; m < 4; m++) {                                   \
            float xs = xv[m].COMP;                                      \
            acc[m].x = fmaf(xs, w.x, acc[m].x);                         \
            acc[m].y = fmaf(xs, w.y, acc[m].y);                         \
            acc[m].z = fmaf(xs, w.z, acc[m].z);                         \
            acc[m].w = fmaf(xs, w.w, acc[m].w);                         \
        }                                                               \
    }

#pragma unroll 4
    for (int k0 = 0; k0 < 64; k0 += 4) {
        float4 xv[4];
#pragma unroll
        for (int m = 0; m < 4; m++)
            xv[m] = *(const float4*)&Xs[(m * 16 + nl) * XRS1 + k0];
        G1_STEP(0, x)
        G1_STEP(1, y)
        G1_STEP(2, z)
        G1_STEP(3, w)
    }
#undef G1_STEP

#pragma unroll
    for (int m = 0; m < 4; m++) {
        int gn = nbase + m * 16 + nl;
        if (gn >= N) continue;
        float s = g_dinv[gn];
        __half2* o = (__half2*)(g_hp + (size_t)gn * HID + fg4);
        o[0] = __floats2half2_rn(acc[m].x * s, acc[m].y * s);
        o[1] = __floats2half2_rn(acc[m].z * s, acc[m].w * s);
    }
}

// ---------------- fused aggregate + epilogue (+ optional pool) -----------
__global__ void __launch_bounds__(256) k_agg(
        const __half* __restrict__ hp, const float* __restrict__ resid,
        const float* __restrict__ bias, const float* __restrict__ gamma,
        const float* __restrict__ beta, const float* __restrict__ mean,
        const float* __restrict__ var,
        float* __restrict__ hout, const int* __restrict__ batch, int N) {
    int n = (blockIdx.x * blockDim.x + threadIdx.x) >> 5;
    if (n >= N) return;
    const int lane = threadIdx.x & 31;
    const int f = lane * 2;

    const int  start = g_rowptr[n];
    const int  len   = g_cnt[n];
    const int* cs    = g_csr + start;

    float ax = 0.f, ay = 0.f, bx = 0.f, by = 0.f;
    int j = 0;
    for (; j + 8 <= len; j += 8) {
        int s0 = cs[j],     s1 = cs[j + 1], s2 = cs[j + 2], s3 = cs[j + 3];
        int s4 = cs[j + 4], s5 = cs[j + 5], s6 = cs[j + 6], s7 = cs[j + 7];
        float2 v0 = __half22float2(*(const __half2*)(hp + (size_t)s0 * HID + f));
        float2 v1 = __half22float2(*(const __half2*)(hp + (size_t)s1 * HID + f));
        float2 v2 = __half22float2(*(const __half2*)(hp + (size_t)s2 * HID + f));
        float2 v3 = __half22float2(*(const __half2*)(hp + (size_t)s3 * HID + f));
        float2 v4 = __half22float2(*(const __half2*)(hp + (size_t)s4 * HID + f));
        float2 v5 = __half22float2(*(const __half2*)(hp + (size_t)s5 * HID + f));
        float2 v6 = __half22float2(*(const __half2*)(hp + (size_t)s6 * HID + f));
        float2 v7 = __half22float2(*(const __half2*)(hp + (size_t)s7 * HID + f));
        ax += (v0.x + v1.x) + (v4.x + v5.x);
        ay += (v0.y + v1.y) + (v4.y + v5.y);
        bx += (v2.x + v3.x) + (v6.x + v7.x);
        by += (v2.y + v3.y) + (v6.y + v7.y);
    }
    for (; j + 4 <= len; j += 4) {
        int s0 = cs[j], s1 = cs[j + 1], s2 = cs[j + 2], s3 = cs[j + 3];
        float2 v0 = __half22float2(*(const __half2*)(hp + (size_t)s0 * HID + f));
        float2 v1 = __half22float2(*(const __half2*)(hp + (size_t)s1 * HID + f));
        float2 v2 = __half22float2(*(const __half2*)(hp + (size_t)s2 * HID + f));
        float2 v3 = __half22float2(*(const __half2*)(hp + (size_t)s3 * HID + f));
        ax += v0.x + v1.x;
        ay += v0.y + v1.y;
        bx += v2.x + v3.x;
        by += v2.y + v3.y;
    }
    for (; j < len; j++) {
        int s = cs[j];
        float2 v = __half22float2(*(const __half2*)(hp + (size_t)s * HID + f));
        ax += v.x;
        ay += v.y;
    }
    ax += bx; ay += by;

    float di = g_dinv[n];
    float2 p = __half22float2(*(const __half2*)(hp + (size_t)n * HID + f));
    float vx = (ax + p.x) * di + bias[f];
    float vy = (ay + p.y) * di + bias[f + 1];
    vx = (vx - mean[f])     * (gamma[f]     * rsqrtf(var[f]     + BN_EPS)) + beta[f];
    vy = (vy - mean[f + 1]) * (gamma[f + 1] * rsqrtf(var[f + 1] + BN_EPS)) + beta[f + 1];
    vx = fmaxf(vx, 0.f);
    vy = fmaxf(vy, 0.f);
    if (resid) {
        float2 r = *(const float2*)(resid + (size_t)n * HID + f);
        vx += r.x; vy += r.y;
    }
    if (hout)
        *(float2*)(hout + (size_t)n * HID + f) = make_float2(vx, vy);
    if (batch) {
        int g = batch[n];
        red_add_v2(&g_sums[(size_t)g * HID + f], vx, vy);
        if (lane == 0) atomicAdd(&g_cnts[g], 1.0f);
    }
}

// ---------------- final linear ----------------
__global__ void k_final(const float* __restrict__ lin_w, const float* __restrict__ lin_b,
                        float* __restrict__ out, int G) {
    int g = blockIdx.x * blockDim.x + threadIdx.x;
    if (g >= G) return;
    float c = fmaxf(g_cnts[g], 1.0f);
    float acc = 0.f;
#pragma unroll
    for (int f = 0; f < HID; f++) acc += g_sums[g * HID + f] * lin_w[f];
    out[g] = acc / c + lin_b[0];
}

// ---------------- host launcher ----------------
extern "C" void kernel_launch(void* const* d_in, const int* in_sizes, int n_in,
                              void* d_out, int out_size) {
    const float* x     = (const float*)d_in[0];
    const int*   ei    = (const int*)  d_in[1];
    const int*   batch = (const int*)  d_in[2];
    const float* W_in  = (const float*)d_in[3];
    const float* W1    = (const float*)d_in[4];
    const float* b1    = (const float*)d_in[5];
    const float* Ws    = (const float*)d_in[6];
    const float* bs    = (const float*)d_in[7];
    const float* bn_g  = (const float*)d_in[8];
    const float* bn_b  = (const float*)d_in[9];
    const float* bn_m  = (const float*)d_in[10];
    const float* bn_v  = (const float*)d_in[11];
    const float* lin_w = (const float*)d_in[12];
    const float* lin_b = (const float*)d_in[13];
    float* out = (float*)d_out;

    const int N = in_sizes[0] / NF;
    const int E = in_sizes[1] / 2;
    const int G = out_size;
    const int* src = ei;
    const int* dst = ei + E;

    float  *p_id, *p_h;
    int    *p_cnt;
    __half *p_hp;
    cudaGetSymbolAddress((void**)&p_id,  g_id);
    cudaGetSymbolAddress((void**)&p_h,   g_h);
    cudaGetSymbolAddress((void**)&p_hp,  g_hp);
    cudaGetSymbolAddress((void**)&p_cnt, g_cnt);

    const int smem0 = (64 * XRS0 + 128 * WRS0) * 4;   // 103424 B
    static bool attr_done = false;
    if (!attr_done) {
        cudaFuncSetAttribute(k_gemm0, cudaFuncAttributeMaxDynamicSharedMemorySize, smem0);
        attr_done = true;
    }

    const int thr = 256;
    const int eb4 = (E / 4 + thr - 1) / thr + 1;
    const int gemmB = (N + 63) / 64;

    cudaMemsetAsync(p_cnt, 0, (size_t)N * sizeof(int), 0);   // graph memset node
    k_hist   <<<eb4, thr>>>(dst, E, G);
    k_scanall<<<1, 1024>>>(N);
    k_gemm0  <<<gemmB, 512, smem0>>>(x, W_in, W1, N);   // 4th launch: profiled
    k_fill   <<<eb4, thr>>>(src, dst, E);

    const int aggB = (N * 32 + thr - 1) / thr;
    for (int layer = 0; layer < 5; layer++) {
        if (layer > 0)
            k_gemm64<<<gemmB, 256>>>(p_h, Ws + (size_t)(layer - 1) * HID * HID, N);
        const float* bias  = (layer == 0) ? b1 : bs + (size_t)(layer - 1) * HID;
        const float* resid = (layer == 0) ? p_id : (layer < 4 ? p_h : nullptr);
        float*       hout  = (layer < 4) ? p_h : nullptr;
        const int*   bptr  = (layer == 4) ? batch : nullptr;
        k_agg<<<aggB, thr>>>(p_hp, resid, bias,
                             bn_g + layer * HID, bn_b + layer * HID,
                             bn_m + layer * HID, bn_v + layer * HID,
                             hout, bptr, N);
    }

    k_final<<<1, ((G + 31) / 32) * 32>>>(lin_w, lin_b, out, G);
}

// round 13
// speedup vs baseline: 1.3630x; 1.2695x over previous
#include <cuda_runtime.h>
#include <cuda_fp16.h>
#include <math.h>

#define NF 128
#define HID 64
#define MAXN 50000
#define MAXE 800000
#define MAXG 64
#define BN_EPS 1e-5f

// ---- static scratch ----
__device__ int    g_cnt   [MAXN];
__device__ int    g_rowptr[MAXN];
__device__ int    g_cursor[MAXN];
__device__ float  g_dinv  [MAXN];
__device__ int    g_csr   [MAXE];
__device__ float  g_id    [MAXN * HID];    // fp32 input projection (residual)
__device__ __half g_hp    [MAXN * HID];    // fp16 pre-scaled (h@W)*dinv
__device__ float  g_h     [MAXN * HID];    // fp32 layer state
__device__ float  g_sums  [MAXG * HID];
__device__ float  g_cnts  [MAXG];

__device__ __forceinline__ void red_add_v2(float* addr, float a, float b) {
    asm volatile("red.global.add.v2.f32 [%0], {%1,%2};"
                 :: "l"(addr), "f"(a), "f"(b) : "memory");
}

// ---------------- setup ----------------
__global__ void k_hist(const int* __restrict__ dst, int E, int G) {
    int i = blockIdx.x * blockDim.x + threadIdx.x;
    int e = i * 8;
    if (e + 7 < E) {
#pragma unroll
        for (int j = 0; j < 8; j++) atomicAdd(&g_cnt[dst[e + j]], 1);
    } else {
        for (int j = e; j < E; j++) atomicAdd(&g_cnt[dst[j]], 1);
    }
    if (i < G * HID) g_sums[i] = 0.0f;
    if (i < G) g_cnts[i] = 0.0f;
}

// dinv from degree counts only (no scan dependency)
__global__ void k_dinv(int N) {
    int i = blockIdx.x * blockDim.x + threadIdx.x;
    if (i < N) g_dinv[i] = rsqrtf((float)g_cnt[i] + 1.0f);  // +1 self-loop
}

// single-block exclusive scan of g_cnt -> rowptr/cursor
__global__ void k_scanall(int N) {
    __shared__ int sh[1024];
    const int t = threadIdx.x;
    const int per = (N + 1023) / 1024;
    const int base = t * per;
    int s = 0;
    for (int i = 0; i < per; i++) {
        int idx = base + i;
        if (idx < N) s += g_cnt[idx];
    }
    sh[t] = s;
    __syncthreads();
    for (int off = 1; off < 1024; off <<= 1) {
        int v = (t >= off) ? sh[t - off] : 0;
        __syncthreads();
        sh[t] += v;
        __syncthreads();
    }
    int run = sh[t] - s;
    for (int i = 0; i < per; i++) {
        int idx = base + i;
        if (idx < N) {
            int c = g_cnt[idx];
            g_rowptr[idx] = run;
            g_cursor[idx] = run;
            run += c;
        }
    }
}

__global__ void k_fill(const int* __restrict__ src, const int* __restrict__ dst, int E) {
    int i = blockIdx.x * blockDim.x + threadIdx.x;
    int e = i * 8;
    if (e + 7 < E) {
        int d[8], sr[8], p[8];
#pragma unroll
        for (int j = 0; j < 8; j++) { d[j] = dst[e + j]; sr[j] = src[e + j]; }
#pragma unroll
        for (int j = 0; j < 8; j++) p[j] = atomicAdd(&g_cursor[d[j]], 1);
#pragma unroll
        for (int j = 0; j < 8; j++) g_csr[p[j]] = sr[j];
    } else {
        for (int j = e; j < E; j++) {
            int pp = atomicAdd(&g_cursor[dst[j]], 1);
            g_csr[pp] = src[j];
        }
    }
}

// ------- fused dual GEMM (K=128): id = X@W_in^T (fp32), hp = (X@W1^T)*dinv (fp16)
// 512 threads, 64 nodes/block, 128 output feats, thread = 4 nodes x 4 feats.
#define XRS0 132
#define WRS0 136
__global__ void __launch_bounds__(512) k_gemm0(const float* __restrict__ X,
                                               const float* __restrict__ W_in,
                                               const float* __restrict__ W1,
                                               int N) {
    extern __shared__ float sm0[];
    float* Xs = sm0;               // [64][XRS0]
    float* Wt = sm0 + 64 * XRS0;   // [128][WRS0]: Wt[k][f]

    const int tid = threadIdx.x;
    const int nbase = blockIdx.x * 64;

    for (int idx = tid; idx < 128 * 128; idx += 512) {
        int f = idx >> 7;
        int k = idx & 127;
        float v = (f < 64) ? W_in[f * 128 + k] : W1[(f - 64) * 128 + k];
        Wt[k * WRS0 + f] = v;
    }
    for (int idx = tid; idx < 64 * 32; idx += 512) {
        int node = idx >> 5;
        int kq = (idx & 31) * 4;
        int gn = nbase + node;
        float4 v = (gn < N) ? *(const float4*)(X + (size_t)gn * 128 + kq)
                            : make_float4(0.f, 0.f, 0.f, 0.f);
        *(float4*)&Xs[node * XRS0 + kq] = v;
    }
    __syncthreads();

    const int fg4 = (tid & 31) * 4;   // 0..124
    const int nl  = tid >> 5;         // 0..15 (warp-uniform)

    float4 acc[4];
#pragma unroll
    for (int m = 0; m < 4; m++) acc[m] = make_float4(0.f, 0.f, 0.f, 0.f);

#define G0_STEP(J, COMP)                                                \
    {                                                                   \
        float4 w = *(const float4*)&Wt[(k0 + J) * WRS0 + fg4];          \
        _Pragma("unroll")                                               \
        for (int m = 0; m < 4; m++) {                                   \
            float xs = xv[m].COMP;                                      \
            acc[m].x = fmaf(xs, w.x, acc[m].x);                         \
            acc[m].y = fmaf(xs, w.y, acc[m].y);                         \
            acc[m].z = fmaf(xs, w.z, acc[m].z);                         \
            acc[m].w = fmaf(xs, w.w, acc[m].w);                         \
        }                                                               \
    }

#pragma unroll 4
    for (int k0 = 0; k0 < 128; k0 += 4) {
        float4 xv[4];
#pragma unroll
        for (int m = 0; m < 4; m++)
            xv[m] = *(const float4*)&Xs[(m * 16 + nl) * XRS0 + k0];
        G0_STEP(0, x)
        G0_STEP(1, y)
        G0_STEP(2, z)
        G0_STEP(3, w)
    }
#undef G0_STEP

#pragma unroll
    for (int m = 0; m < 4; m++) {
        int gn = nbase + m * 16 + nl;
        if (gn >= N) continue;
        if (fg4 < 64) {
            *(float4*)(g_id + (size_t)gn * HID + fg4) = acc[m];
        } else {
            float s = g_dinv[gn];
            __half2* o = (__half2*)(g_hp + (size_t)gn * HID + (fg4 - 64));
            o[0] = __floats2half2_rn(acc[m].x * s, acc[m].y * s);
            o[1] = __floats2half2_rn(acc[m].z * s, acc[m].w * s);
        }
    }
}

// ------- layer GEMM (K=64): hp = (h@W^T)*dinv (fp16); X staged in smem -----
#define XRS1 68
#define WRS1 72
__global__ void __launch_bounds__(256) k_gemm64(const float* __restrict__ X,
                                                const float* __restrict__ W,
                                                int N) {
    __shared__ float Xs[64 * XRS1];
    __shared__ float Wt[64 * WRS1];   // Wt[k][f]

    const int tid = threadIdx.x;
    const int nbase = blockIdx.x * 64;

    for (int idx = tid; idx < 64 * 64; idx += 256) {
        int f = idx >> 6;
        int k = idx & 63;
        Wt[k * WRS1 + f] = W[idx];
    }
    for (int idx = tid; idx < 64 * 16; idx += 256) {
        int node = idx >> 4;
        int kq = (idx & 15) * 4;
        int gn = nbase + node;
        float4 v = (gn < N) ? *(const float4*)(X + (size_t)gn * 64 + kq)
                            : make_float4(0.f, 0.f, 0.f, 0.f);
        *(float4*)&Xs[node * XRS1 + kq] = v;
    }
    __syncthreads();

    const int fg4 = (tid & 15) * 4;   // 0..60
    const int nl  = tid >> 4;         // 0..15

    float4 acc[4];
#pragma unroll
    for (int m = 0; m < 4; m++) acc[m] = make_float4(0.f, 0.f, 0.f, 0.f);

#define G1_STEP(J, COMP)                                                \
    {                                                                   \
        float4 w = *(const float4*)&Wt[(k0 + J) * WRS1 + fg4];          \
        _Pragma("unroll")                                               \
        for (int m = 0; m < 4; m++) {                                   \
            float xs = xv[m].COMP;                                      \
            acc[m].x = fmaf(xs, w.x, acc[m].x);                         \
            acc[m].y = fmaf(xs, w.y, acc[m].y);                         \
            acc[m].z = fmaf(xs, w.z, acc[m].z);                         \
            acc[m].w = fmaf(xs, w.w, acc[m].w);                         \
        }                                                               \
    }

#pragma unroll 4
    for (int k0 = 0; k0 < 64; k0 += 4) {
        float4 xv[4];
#pragma unroll
        for (int m = 0; m < 4; m++)
            xv[m] = *(const float4*)&Xs[(m * 16 + nl) * XRS1 + k0];
        G1_STEP(0, x)
        G1_STEP(1, y)
        G1_STEP(2, z)
        G1_STEP(3, w)
    }
#undef G1_STEP

#pragma unroll
    for (int m = 0; m < 4; m++) {
        int gn = nbase + m * 16 + nl;
        if (gn >= N) continue;
        float s = g_dinv[gn];
        __half2* o = (__half2*)(g_hp + (size_t)gn * HID + fg4);
        o[0] = __floats2half2_rn(acc[m].x * s, acc[m].y * s);
        o[1] = __floats2half2_rn(acc[m].z * s, acc[m].w * s);
    }
}

// ---------------- fused aggregate + epilogue (+ optional pool) -----------
__global__ void __launch_bounds__(256) k_agg(
        const __half* __restrict__ hp, const float* __restrict__ resid,
        const float* __restrict__ bias, const float* __restrict__ gamma,
        const float* __restrict__ beta, const float* __restrict__ mean,
        const float* __restrict__ var,
        float* __restrict__ hout, const int* __restrict__ batch, int N) {
    int n = (blockIdx.x * blockDim.x + threadIdx.x) >> 5;
    if (n >= N) return;
    const int lane = threadIdx.x & 31;
    const int f = lane * 2;

    const int  start = g_rowptr[n];
    const int  len   = g_cnt[n];
    const int* cs    = g_csr + start;

    float ax = 0.f, ay = 0.f, bx = 0.f, by = 0.f;
    int j = 0;
    for (; j + 8 <= len; j += 8) {
        int s0 = cs[j],     s1 = cs[j + 1], s2 = cs[j + 2], s3 = cs[j + 3];
        int s4 = cs[j + 4], s5 = cs[j + 5], s6 = cs[j + 6], s7 = cs[j + 7];
        float2 v0 = __half22float2(*(const __half2*)(hp + (size_t)s0 * HID + f));
        float2 v1 = __half22float2(*(const __half2*)(hp + (size_t)s1 * HID + f));
        float2 v2 = __half22float2(*(const __half2*)(hp + (size_t)s2 * HID + f));
        float2 v3 = __half22float2(*(const __half2*)(hp + (size_t)s3 * HID + f));
        float2 v4 = __half22float2(*(const __half2*)(hp + (size_t)s4 * HID + f));
        float2 v5 = __half22float2(*(const __half2*)(hp + (size_t)s5 * HID + f));
        float2 v6 = __half22float2(*(const __half2*)(hp + (size_t)s6 * HID + f));
        float2 v7 = __half22float2(*(const __half2*)(hp + (size_t)s7 * HID + f));
        ax += (v0.x + v1.x) + (v4.x + v5.x);
        ay += (v0.y + v1.y) + (v4.y + v5.y);
        bx += (v2.x + v3.x) + (v6.x + v7.x);
        by += (v2.y + v3.y) + (v6.y + v7.y);
    }
    for (; j + 4 <= len; j += 4) {
        int s0 = cs[j], s1 = cs[j + 1], s2 = cs[j + 2], s3 = cs[j + 3];
        float2 v0 = __half22float2(*(const __half2*)(hp + (size_t)s0 * HID + f));
        float2 v1 = __half22float2(*(const __half2*)(hp + (size_t)s1 * HID + f));
        float2 v2 = __half22float2(*(const __half2*)(hp + (size_t)s2 * HID + f));
        float2 v3 = __half22float2(*(const __half2*)(hp + (size_t)s3 * HID + f));
        ax += v0.x + v1.x;
        ay += v0.y + v1.y;
        bx += v2.x + v3.x;
        by += v2.y + v3.y;
    }
    for (; j < len; j++) {
        int s = cs[j];
        float2 v = __half22float2(*(const __half2*)(hp + (size_t)s * HID + f));
        ax += v.x;
        ay += v.y;
    }
    ax += bx; ay += by;

    float di = g_dinv[n];
    float2 p = __half22float2(*(const __half2*)(hp + (size_t)n * HID + f));
    float vx = (ax + p.x) * di + bias[f];
    float vy = (ay + p.y) * di + bias[f + 1];
    vx = (vx - mean[f])     * (gamma[f]     * rsqrtf(var[f]     + BN_EPS)) + beta[f];
    vy = (vy - mean[f + 1]) * (gamma[f + 1] * rsqrtf(var[f + 1] + BN_EPS)) + beta[f + 1];
    vx = fmaxf(vx, 0.f);
    vy = fmaxf(vy, 0.f);
    if (resid) {
        float2 r = *(const float2*)(resid + (size_t)n * HID + f);
        vx += r.x; vy += r.y;
    }
    if (hout)
        *(float2*)(hout + (size_t)n * HID + f) = make_float2(vx, vy);
    if (batch) {
        int g = batch[n];
        red_add_v2(&g_sums[(size_t)g * HID + f], vx, vy);
        if (lane == 0) atomicAdd(&g_cnts[g], 1.0f);
    }
}

// ---------------- final linear ----------------
__global__ void k_final(const float* __restrict__ lin_w, const float* __restrict__ lin_b,
                        float* __restrict__ out, int G) {
    int g = blockIdx.x * blockDim.x + threadIdx.x;
    if (g >= G) return;
    float c = fmaxf(g_cnts[g], 1.0f);
    float acc = 0.f;
#pragma unroll
    for (int f = 0; f < HID; f++) acc += g_sums[g * HID + f] * lin_w[f];
    out[g] = acc / c + lin_b[0];
}

// ---------------- host launcher ----------------
extern "C" void kernel_launch(void* const* d_in, const int* in_sizes, int n_in,
                              void* d_out, int out_size) {
    const float* x     = (const float*)d_in[0];
    const int*   ei    = (const int*)  d_in[1];
    const int*   batch = (const int*)  d_in[2];
    const float* W_in  = (const float*)d_in[3];
    const float* W1    = (const float*)d_in[4];
    const float* b1    = (const float*)d_in[5];
    const float* Ws    = (const float*)d_in[6];
    const float* bs    = (const float*)d_in[7];
    const float* bn_g  = (const float*)d_in[8];
    const float* bn_b  = (const float*)d_in[9];
    const float* bn_m  = (const float*)d_in[10];
    const float* bn_v  = (const float*)d_in[11];
    const float* lin_w = (const float*)d_in[12];
    const float* lin_b = (const float*)d_in[13];
    float* out = (float*)d_out;

    const int N = in_sizes[0] / NF;
    const int E = in_sizes[1] / 2;
    const int G = out_size;
    const int* src = ei;
    const int* dst = ei + E;

    float  *p_id, *p_h;
    int    *p_cnt;
    __half *p_hp;
    cudaGetSymbolAddress((void**)&p_id,  g_id);
    cudaGetSymbolAddress((void**)&p_h,   g_h);
    cudaGetSymbolAddress((void**)&p_hp,  g_hp);
    cudaGetSymbolAddress((void**)&p_cnt, g_cnt);

    const int smem0 = (64 * XRS0 + 128 * WRS0) * 4;   // 103424 B
    static bool init_done = false;
    static cudaStream_t s_side = nullptr;
    static cudaEvent_t ev_fork = nullptr, ev_join = nullptr;
    if (!init_done) {
        cudaFuncSetAttribute(k_gemm0, cudaFuncAttributeMaxDynamicSharedMemorySize, smem0);
        cudaStreamCreateWithFlags(&s_side, cudaStreamNonBlocking);
        cudaEventCreateWithFlags(&ev_fork, cudaEventDisableTiming);
        cudaEventCreateWithFlags(&ev_join, cudaEventDisableTiming);
        init_done = true;
    }

    const int thr = 256;
    const int eb8 = (E / 8 + thr - 1) / thr + 1;
    const int gemmB = (N + 63) / 64;

    // main stream: counts -> dinv
    cudaMemsetAsync(p_cnt, 0, (size_t)N * sizeof(int), 0);
    k_hist<<<eb8, thr>>>(dst, E, G);
    k_dinv<<<(N + thr - 1) / thr, thr>>>(N);

    // fork: side stream builds CSR (scan + fill) while main runs gemm0
    cudaEventRecord(ev_fork, 0);
    cudaStreamWaitEvent(s_side, ev_fork, 0);
    k_scanall<<<1, 1024, 0, s_side>>>(N);
    k_fill   <<<eb8, thr, 0, s_side>>>(src, dst, E);
    cudaEventRecord(ev_join, s_side);

    k_gemm0<<<gemmB, 512, smem0>>>(x, W_in, W1, N);   // overlaps CSR build

    cudaStreamWaitEvent(0, ev_join, 0);               // join before first agg

    const int aggB = (N * 32 + thr - 1) / thr;
    for (int layer = 0; layer < 5; layer++) {
        if (layer > 0)
            k_gemm64<<<gemmB, 256>>>(p_h, Ws + (size_t)(layer - 1) * HID * HID, N);
        const float* bias  = (layer == 0) ? b1 : bs + (size_t)(layer - 1) * HID;
        const float* resid = (layer == 0) ? p_id : (layer < 4 ? p_h : nullptr);
        float*       hout  = (layer < 4) ? p_h : nullptr;
        const int*   bptr  = (layer == 4) ? batch : nullptr;
        k_agg<<<aggB, thr>>>(p_hp, resid, bias,
                             bn_g + layer * HID, bn_b + layer * HID,
                             bn_m + layer * HID, bn_v + layer * HID,
                             hout, bptr, N);
    }

    k_final<<<1, ((G + 31) / 32) * 32>>>(lin_w, lin_b, out, G);
}